// round 12
// baseline (speedup 1.0000x reference)
#include <cuda_runtime.h>

// ---------------------------------------------------------------------------
// 2-layer KAN (1 -> 8 -> 1) == scalar function out = f(x).
// PDL-chained pair, minimized total cycles:
//   (1) build_lut_kernel: ONE block x 288 threads. Stages prescaled
//       zero-padded weight tables to smem, then each thread does exactly one
//       exact node eval (nodes -1..257), forming a piecewise-cubic LUT of f
//       on [-8,8) with N=256 intervals (h=1/16 exact) -> g_coef (4KB).
//       Fires the programmatic-launch trigger right after publishing.
//   (2) kan_lut_kernel (ProgrammaticStreamSerialization): 512 blocks x 256.
//       Issues its x LDG first (overlaps the build tail), then
//       cudaGridDependencySynchronize(), stages the 4KB LUT (one float4 per
//       thread), and evaluates: k=floor((x+8)*16), LDS.128 + Horner.
// Exact fallback for |x|>=8 (never hit for N(0,1) inputs).
// ---------------------------------------------------------------------------

#define LUT_N    256
#define LUT_INVH 16.0f          // 1/h, exact
#define LUT_H    (1.0f / 16.0f) // h,   exact
#define LUT_OFS  128.0f         // 8*16, exact
#define NODES    259            // node indices -1..257
#define BTPB     288            // build kernel threads (9 warps)

__device__ __align__(16) float4 g_coef[LUT_N];

__device__ __forceinline__ float silu_f(float x) {
    return x * __fdividef(1.0f, 1.0f + __expf(-x));
}

__device__ __forceinline__ void spline_basis(float s, float jf, float* b) {
    const float c6 = 1.0f / 6.0f;
    float t = s - jf;
    float u = 1.0f - t;
    float t2 = t * t, t3 = t2 * t;
    b[0] = u * u * u * c6;
    b[1] = (3.0f * t3 - 6.0f * t2 + 4.0f) * c6;
    b[2] = (-3.0f * t3 + 3.0f * t2 + 3.0f * t + 1.0f) * c6;
    b[3] = t3 * c6;
}

// Exact KAN eval from prescaled zero-padded smem tables (no inner bounds
// checks: row/col = spline index + 3, pads are zero == clipped bases).
__device__ __forceinline__ float kan_eval_smem(
    float x,
    const float (*s_w1t)[8],      // [14][8]: row r -> ri=r-3, prescaled sc1
    const float (*s_w2)[16],      // [8][16]: col c -> ri=c-3, prescaled sc2
    const float* s_bw1, const float* s_bw2)
{
    float si = silu_f(x);
    float h[8];
    #pragma unroll
    for (int o = 0; o < 8; o++) h[o] = si * s_bw1[o];

    float s  = (x + 2.2f) * 2.5f;
    float jf = floorf(s);
    int j = (int)jf;
    if (j >= 0 && j <= 10) {
        float b[4];
        spline_basis(s, jf, b);
        #pragma unroll
        for (int m = 0; m < 4; m++) {
            const float* row = s_w1t[j + m];   // (j-3+m)+3 in [0,13]
            float bm = b[m];
            #pragma unroll
            for (int o = 0; o < 8; o++) h[o] = fmaf(bm, row[o], h[o]);
        }
    }

    float acc = 0.0f;
    #pragma unroll
    for (int i = 0; i < 8; i++) {
        float hv = h[i];
        acc += silu_f(hv) * s_bw2[i];
        float s2  = (hv + 2.2f) * 2.5f;
        float jf2 = floorf(s2);
        int j2 = (int)jf2;
        if (j2 >= 0 && j2 <= 10) {
            float b[4];
            spline_basis(s2, jf2, b);
            const float* row = s_w2[i];
            #pragma unroll
            for (int m = 0; m < 4; m++)
                acc = fmaf(b[m], row[j2 + m], acc);   // col in [0,13]
        }
    }
    return acc;
}

// Shared helper: stage prescaled zero-padded weight tables (needs >=256 thr).
__device__ __forceinline__ void stage_weights(
    int tid,
    float (*s_w1t)[8], float (*s_w2)[16], float* s_bw1, float* s_bw2,
    const float* __restrict__ bw1, const float* __restrict__ sw1,
    const float* __restrict__ sc1, const float* __restrict__ bw2,
    const float* __restrict__ sw2, const float* __restrict__ sc2)
{
    if (tid < 112) {                       // s_w1t: 14 rows x 8 units
        int r = tid >> 3, o = tid & 7, ri = r - 3;
        s_w1t[r][o] = (ri >= 0 && ri < 8) ? __ldg(sw1 + o * 8 + ri) * __ldg(sc1 + o)
                                          : 0.0f;
    } else if (tid < 240) {                // s_w2: 8 units x 16 cols
        int q = tid - 112, i = q >> 4, c = q & 15, ri = c - 3;
        s_w2[i][c] = (ri >= 0 && ri < 8) ? __ldg(sw2 + i * 8 + ri) * __ldg(sc2 + i)
                                         : 0.0f;
    } else if (tid < 248) {
        s_bw1[tid - 240] = __ldg(bw1 + (tid - 240));
    } else if (tid < 256) {
        s_bw2[tid - 248] = __ldg(bw2 + (tid - 248));
    }
}

// Build: ONE block, 288 threads, one exact node eval per thread.
__global__ __launch_bounds__(BTPB)
void build_lut_kernel(
    const float* __restrict__ bw1, const float* __restrict__ sw1,
    const float* __restrict__ sc1, const float* __restrict__ bw2,
    const float* __restrict__ sw2, const float* __restrict__ sc2)
{
    __shared__ float s_y[NODES];
    __shared__ __align__(16) float s_w1t[14][8];
    __shared__ __align__(16) float s_w2[8][16];
    __shared__ float s_bw1[8], s_bw2[8];

    int tid = threadIdx.x;
    stage_weights(tid, s_w1t, s_w2, s_bw1, s_bw2,
                  bw1, sw1, sc1, bw2, sw2, sc2);
    __syncthreads();

    if (tid < NODES) {
        float xn = fmaf((float)(tid - 1), LUT_H, -8.0f);   // exact grid node
        s_y[tid] = kan_eval_smem(xn, s_w1t, s_w2, s_bw1, s_bw2);
    }
    __syncthreads();

    if (tid < LUT_N) {
        float y0 = s_y[tid], y1 = s_y[tid + 1];
        float y2 = s_y[tid + 2], y3 = s_y[tid + 3];
        // Lagrange cubic through (u=-1,y0),(0,y1),(1,y2),(2,y3):
        float c0 = y1;
        float c1 = -y0 * (1.0f/3.0f) - 0.5f * y1 + y2 - y3 * (1.0f/6.0f);
        float c2 =  0.5f * y0 - y1 + 0.5f * y2;
        float c3 = (y3 - y0) * (1.0f/6.0f) + 0.5f * (y1 - y2);
        g_coef[tid] = make_float4(c0, c1, c2, c3);
    }
    // Publish LUT, then allow the dependent grid to proceed.
    __threadfence();
    cudaTriggerProgrammaticLaunchCompletion();
}

__global__ __launch_bounds__(256)
void kan_lut_kernel(const float4* __restrict__ xv, float4* __restrict__ outv,
                    const float* __restrict__ bw1, const float* __restrict__ sw1,
                    const float* __restrict__ sc1, const float* __restrict__ bw2,
                    const float* __restrict__ sw2, const float* __restrict__ sc2,
                    int n4)
{
    __shared__ __align__(16) float4 s_lut[LUT_N];

    int tid = threadIdx.x;
    int idx = blockIdx.x * 256 + tid;

    // 1) Independent prelude: issue the x load NOW (overlaps the build tail).
    bool valid = idx < n4;
    float4 xin = valid ? xv[idx] : make_float4(0.f, 0.f, 0.f, 0.f);

    // 2) Wait for the primary (build) grid's writes to be visible.
    cudaGridDependencySynchronize();

    // 3) Stage LUT: 256 float4 / 256 threads = ONE per thread, coalesced.
    s_lut[tid] = __ldcg(&g_coef[tid]);
    __syncthreads();

    // 4) Evaluate: one random LDS.128 + Horner per element.
    float xs[4] = {xin.x, xin.y, xin.z, xin.w};
    float r[4];
    bool oor_any = false;
    unsigned oor_mask = 0;

    #pragma unroll
    for (int e = 0; e < 4; e++) {
        float x = xs[e];
        float s = fmaf(x, LUT_INVH, LUT_OFS);
        float kf = floorf(s);
        int k = (int)kf;
        bool oo = (k < 0) | (k >= LUT_N);
        oor_any |= oo;
        if (oo) oor_mask |= 1u << e;
        k = max(0, min(LUT_N - 1, k));
        float u = fmaf(x, LUT_INVH, LUT_OFS - (float)k);
        float4 cf = s_lut[k];
        r[e] = fmaf(fmaf(fmaf(cf.w, u, cf.z), u, cf.y), u, cf.x);
    }

    if (oor_any) {   // essentially never taken for N(0,1) inputs
        // Rare path: exact eval straight from global weights.
        #pragma unroll
        for (int e = 0; e < 4; e++) {
            if (!(oor_mask & (1u << e))) continue;
            float x = xs[e];
            float acc = 0.0f;
            for (int u2 = 0; u2 < 8; u2++) {
                float h = silu_f(x) * __ldg(bw1 + u2);
                float s = (x + 2.2f) * 2.5f;
                float jf = floorf(s);
                int j = (int)jf;
                if (j >= 0 && j <= 10) {
                    float b[4];
                    spline_basis(s, jf, b);
                    float sc = __ldg(sc1 + u2);
                    for (int m = 0; m < 4; m++) {
                        int ri = j - 3 + m;
                        if (ri >= 0 && ri < 8)
                            h += b[m] * __ldg(sw1 + u2 * 8 + ri) * sc;
                    }
                }
                acc += silu_f(h) * __ldg(bw2 + u2);
                float s2 = (h + 2.2f) * 2.5f;
                float jf2 = floorf(s2);
                int j2 = (int)jf2;
                if (j2 >= 0 && j2 <= 10) {
                    float b[4];
                    spline_basis(s2, jf2, b);
                    float sc = __ldg(sc2 + u2);
                    for (int m = 0; m < 4; m++) {
                        int ri = j2 - 3 + m;
                        if (ri >= 0 && ri < 8)
                            acc += b[m] * __ldg(sw2 + u2 * 8 + ri) * sc;
                    }
                }
            }
            r[e] = acc;
        }
    }

    if (valid) outv[idx] = make_float4(r[0], r[1], r[2], r[3]);
}

extern "C" void kernel_launch(void* const* d_in, const int* in_sizes, int n_in,
                              void* d_out, int out_size) {
    const float* x   = (const float*)d_in[0];
    const float* bw1 = (const float*)d_in[1];
    const float* sw1 = (const float*)d_in[2];
    const float* sc1 = (const float*)d_in[3];
    const float* bw2 = (const float*)d_in[4];
    const float* sw2 = (const float*)d_in[5];
    const float* sc2 = (const float*)d_in[6];

    int n  = in_sizes[0];   // 524288
    int n4 = n / 4;         // 131072

    build_lut_kernel<<<1, BTPB>>>(bw1, sw1, sc1, bw2, sw2, sc2);

    // Dependent launch: grid may launch while the build kernel drains;
    // correctness via cudaGridDependencySynchronize() inside the kernel.
    cudaLaunchConfig_t cfg = {};
    cfg.gridDim  = dim3((unsigned)((n4 + 255) / 256), 1, 1);   // 512
    cfg.blockDim = dim3(256, 1, 1);
    cfg.dynamicSmemBytes = 0;
    cfg.stream = 0;
    cudaLaunchAttribute attrs[1];
    attrs[0].id = cudaLaunchAttributeProgrammaticStreamSerialization;
    attrs[0].val.programmaticStreamSerializationAllowed = 1;
    cfg.attrs = attrs;
    cfg.numAttrs = 1;

    cudaLaunchKernelEx(&cfg, kan_lut_kernel,
                       (const float4*)x, (float4*)d_out,
                       bw1, sw1, sc1, bw2, sw2, sc2, n4);
}

// round 13
// speedup vs baseline: 1.0294x; 1.0294x over previous
#include <cuda_runtime.h>

// ---------------------------------------------------------------------------
// 2-layer KAN (1 -> 8 -> 1) == scalar function out = f(x).
// SINGLE fused kernel, minimal redundancy:
//   128 blocks x 512 threads. Each block rebuilds the full N=256-interval
//   piecewise-cubic LUT of f on [-8,8) (h=1/16 exact) in shared memory:
//   threads 0..258 do exactly ONE exact node eval each (nodes -1..257).
//   Redundant build issue cost: <=1 block/SM -> ~560 cyc/SM.
//   Eval: each thread owns 2 float4 (128*512*2*4 = 524288 = B exactly):
//   k=floor((x+8)*16), one LDS.128 + Horner per element.
//   x loads issued first so DRAM latency hides under the build phase.
// Exact fallback (same smem tables) for |x|>=8 — never hit for N(0,1).
// ---------------------------------------------------------------------------

#define LUT_N    256
#define LUT_INVH 16.0f          // 1/h, exact
#define LUT_H    (1.0f / 16.0f) // h,   exact
#define LUT_OFS  128.0f         // 8*16, exact
#define NODES    259            // node indices -1..257
#define TPB      512            // 16 warps
#define F4_PER_T 2              // float4 per thread (eval phase)

__device__ __forceinline__ float silu_f(float x) {
    return x * __fdividef(1.0f, 1.0f + __expf(-x));
}

__device__ __forceinline__ void spline_basis(float s, float jf, float* b) {
    const float c6 = 1.0f / 6.0f;
    float t = s - jf;
    float u = 1.0f - t;
    float t2 = t * t, t3 = t2 * t;
    b[0] = u * u * u * c6;
    b[1] = (3.0f * t3 - 6.0f * t2 + 4.0f) * c6;
    b[2] = (-3.0f * t3 + 3.0f * t2 + 3.0f * t + 1.0f) * c6;
    b[3] = t3 * c6;
}

// Exact KAN eval from prescaled zero-padded smem tables (no inner bounds
// checks: row/col = spline index + 3, pads are zero == clipped bases).
__device__ __forceinline__ float kan_eval_smem(
    float x,
    const float (*s_w1t)[8],      // [14][8]: row r -> ri=r-3, prescaled sc1
    const float (*s_w2)[16],      // [8][16]: col c -> ri=c-3, prescaled sc2
    const float* s_bw1, const float* s_bw2)
{
    float si = silu_f(x);
    float h[8];
    #pragma unroll
    for (int o = 0; o < 8; o++) h[o] = si * s_bw1[o];

    float s  = (x + 2.2f) * 2.5f;
    float jf = floorf(s);
    int j = (int)jf;
    if (j >= 0 && j <= 10) {
        float b[4];
        spline_basis(s, jf, b);
        #pragma unroll
        for (int m = 0; m < 4; m++) {
            const float* row = s_w1t[j + m];   // (j-3+m)+3 in [0,13]
            float bm = b[m];
            #pragma unroll
            for (int o = 0; o < 8; o++) h[o] = fmaf(bm, row[o], h[o]);
        }
    }

    float acc = 0.0f;
    #pragma unroll
    for (int i = 0; i < 8; i++) {
        float hv = h[i];
        acc += silu_f(hv) * s_bw2[i];
        float s2  = (hv + 2.2f) * 2.5f;
        float jf2 = floorf(s2);
        int j2 = (int)jf2;
        if (j2 >= 0 && j2 <= 10) {
            float b[4];
            spline_basis(s2, jf2, b);
            const float* row = s_w2[i];
            #pragma unroll
            for (int m = 0; m < 4; m++)
                acc = fmaf(b[m], row[j2 + m], acc);   // col in [0,13]
        }
    }
    return acc;
}

__global__ __launch_bounds__(TPB)
void kan_fused_kernel(const float4* __restrict__ xv, float4* __restrict__ outv,
                      const float* __restrict__ bw1, const float* __restrict__ sw1,
                      const float* __restrict__ sc1, const float* __restrict__ bw2,
                      const float* __restrict__ sw2, const float* __restrict__ sc2,
                      int n4)
{
    __shared__ __align__(16) float4 s_lut[LUT_N];
    __shared__ float s_y[NODES];
    __shared__ __align__(16) float s_w1t[14][8];
    __shared__ __align__(16) float s_w2[8][16];
    __shared__ float s_bw1[8], s_bw2[8];

    int tid  = threadIdx.x;
    int base = blockIdx.x * (TPB * F4_PER_T) + tid;

    // 1) Issue both x loads immediately (DRAM latency hides under the build).
    int idx0 = base, idx1 = base + TPB;
    bool v0 = idx0 < n4, v1 = idx1 < n4;
    float4 xin0 = v0 ? xv[idx0] : make_float4(0.f, 0.f, 0.f, 0.f);
    float4 xin1 = v1 ? xv[idx1] : make_float4(0.f, 0.f, 0.f, 0.f);

    // 2) Stage prescaled, zero-padded weight tables.
    if (tid < 112) {                       // s_w1t: 14 rows x 8 units
        int r = tid >> 3, o = tid & 7, ri = r - 3;
        s_w1t[r][o] = (ri >= 0 && ri < 8) ? __ldg(sw1 + o * 8 + ri) * __ldg(sc1 + o)
                                          : 0.0f;
    } else if (tid < 240) {                // s_w2: 8 units x 16 cols
        int q = tid - 112, i = q >> 4, c = q & 15, ri = c - 3;
        s_w2[i][c] = (ri >= 0 && ri < 8) ? __ldg(sw2 + i * 8 + ri) * __ldg(sc2 + i)
                                         : 0.0f;
    } else if (tid < 248) {
        s_bw1[tid - 240] = __ldg(bw1 + (tid - 240));
    } else if (tid < 256) {
        s_bw2[tid - 248] = __ldg(bw2 + (tid - 248));
    }
    __syncthreads();

    // 3) Build: exactly ONE node eval per thread (tid 0..258 -> node tid-1).
    if (tid < NODES) {
        float xn = fmaf((float)(tid - 1), LUT_H, -8.0f);   // exact grid node
        s_y[tid] = kan_eval_smem(xn, s_w1t, s_w2, s_bw1, s_bw2);
    }
    __syncthreads();

    // 4) Coefficients: interval k=tid from nodes k-1..k+2 = s_y[tid..tid+3].
    if (tid < LUT_N) {
        float y0 = s_y[tid], y1 = s_y[tid + 1];
        float y2 = s_y[tid + 2], y3 = s_y[tid + 3];
        // Lagrange cubic through (u=-1,y0),(0,y1),(1,y2),(2,y3):
        float c0 = y1;
        float c1 = -y0 * (1.0f/3.0f) - 0.5f * y1 + y2 - y3 * (1.0f/6.0f);
        float c2 =  0.5f * y0 - y1 + 0.5f * y2;
        float c3 = (y3 - y0) * (1.0f/6.0f) + 0.5f * (y1 - y2);
        s_lut[tid] = make_float4(c0, c1, c2, c3);
    }
    __syncthreads();

    // 5) Evaluate 8 elements (2 float4): one random LDS.128 + Horner each.
    float4 xs[F4_PER_T] = {xin0, xin1};
    float4 res[F4_PER_T];
    bool oor_any = false;
    unsigned oor_mask = 0;

    #pragma unroll
    for (int jb = 0; jb < F4_PER_T; jb++) {
        float xi[4] = {xs[jb].x, xs[jb].y, xs[jb].z, xs[jb].w};
        float r[4];
        #pragma unroll
        for (int e = 0; e < 4; e++) {
            float x = xi[e];
            float s = fmaf(x, LUT_INVH, LUT_OFS);
            float kf = floorf(s);
            int k = (int)kf;
            bool oo = (k < 0) | (k >= LUT_N);
            oor_any |= oo;
            if (oo) oor_mask |= 1u << (jb * 4 + e);
            k = max(0, min(LUT_N - 1, k));
            float u = fmaf(x, LUT_INVH, LUT_OFS - (float)k);
            float4 cf = s_lut[k];
            r[e] = fmaf(fmaf(fmaf(cf.w, u, cf.z), u, cf.y), u, cf.x);
        }
        res[jb] = make_float4(r[0], r[1], r[2], r[3]);
    }

    if (oor_any) {   // essentially never taken for N(0,1) inputs
        #pragma unroll
        for (int jb = 0; jb < F4_PER_T; jb++) {
            float* rp = (float*)&res[jb];
            const float* xp = (const float*)&xs[jb];
            #pragma unroll
            for (int e = 0; e < 4; e++)
                if (oor_mask & (1u << (jb * 4 + e)))
                    rp[e] = kan_eval_smem(xp[e], s_w1t, s_w2, s_bw1, s_bw2);
        }
    }

    if (v0) outv[idx0] = res[0];
    if (v1) outv[idx1] = res[1];
}

extern "C" void kernel_launch(void* const* d_in, const int* in_sizes, int n_in,
                              void* d_out, int out_size) {
    const float* x   = (const float*)d_in[0];
    const float* bw1 = (const float*)d_in[1];
    const float* sw1 = (const float*)d_in[2];
    const float* sc1 = (const float*)d_in[3];
    const float* bw2 = (const float*)d_in[4];
    const float* sw2 = (const float*)d_in[5];
    const float* sc2 = (const float*)d_in[6];

    int n  = in_sizes[0];   // 524288
    int n4 = n / 4;         // 131072

    int per_block = TPB * F4_PER_T;                  // 1024 float4
    int blocks = (n4 + per_block - 1) / per_block;   // 128
    kan_fused_kernel<<<blocks, TPB>>>((const float4*)x, (float4*)d_out,
                                      bw1, sw1, sc1, bw2, sw2, sc2, n4);
}

// round 14
// speedup vs baseline: 1.0606x; 1.0303x over previous
#include <cuda_runtime.h>

// ---------------------------------------------------------------------------
// 2-layer KAN (1 -> 8 -> 1) == scalar function out = f(x).
// SINGLE fused kernel, warp-autonomous build (minimal barriers):
//   128 blocks x 512 threads. Each block rebuilds the full N=256-interval
//   piecewise-cubic LUT of f on [-8,8) (h=1/16 exact) in shared memory:
//   warps 0..8 each own 29 intervals; lane l evaluates ONE node (29w-1+l),
//   neighbor node values arrive via shfl_down, lanes 0..28 write the
//   Lagrange cubic coefs straight to s_lut. Only 2 __syncthreads total.
//   Eval: each thread owns 2 float4 (128*512*2*4 = 524288 = B exactly):
//   k=floor((x+8)*16), one LDS.128 + Horner per element.
//   x loads issued first so DRAM latency hides under the build phase.
// Exact fallback (same smem tables) for |x|>=8 — never hit for N(0,1).
// ---------------------------------------------------------------------------

#define LUT_N    256
#define LUT_INVH 16.0f          // 1/h, exact
#define LUT_H    (1.0f / 16.0f) // h,   exact
#define LUT_OFS  128.0f         // 8*16, exact
#define TPB      512            // 16 warps
#define F4_PER_T 2              // float4 per thread (eval phase)
#define BWARPS   9              // build warps: 9*29 = 261 >= 259 nodes

__device__ __forceinline__ float silu_f(float x) {
    return x * __fdividef(1.0f, 1.0f + __expf(-x));
}

__device__ __forceinline__ void spline_basis(float s, float jf, float* b) {
    const float c6 = 1.0f / 6.0f;
    float t = s - jf;
    float u = 1.0f - t;
    float t2 = t * t, t3 = t2 * t;
    b[0] = u * u * u * c6;
    b[1] = (3.0f * t3 - 6.0f * t2 + 4.0f) * c6;
    b[2] = (-3.0f * t3 + 3.0f * t2 + 3.0f * t + 1.0f) * c6;
    b[3] = t3 * c6;
}

// Exact KAN eval from prescaled zero-padded smem tables (no inner bounds
// checks: row/col = spline index + 3, pads are zero == clipped bases).
__device__ __forceinline__ float kan_eval_smem(
    float x,
    const float (*s_w1t)[8],      // [14][8]: row r -> ri=r-3, prescaled sc1
    const float (*s_w2)[16],      // [8][16]: col c -> ri=c-3, prescaled sc2
    const float* s_bw1, const float* s_bw2)
{
    float si = silu_f(x);
    float h[8];
    #pragma unroll
    for (int o = 0; o < 8; o++) h[o] = si * s_bw1[o];

    float s  = (x + 2.2f) * 2.5f;
    float jf = floorf(s);
    int j = (int)jf;
    if (j >= 0 && j <= 10) {
        float b[4];
        spline_basis(s, jf, b);
        #pragma unroll
        for (int m = 0; m < 4; m++) {
            const float* row = s_w1t[j + m];   // (j-3+m)+3 in [0,13]
            float bm = b[m];
            #pragma unroll
            for (int o = 0; o < 8; o++) h[o] = fmaf(bm, row[o], h[o]);
        }
    }

    float acc = 0.0f;
    #pragma unroll
    for (int i = 0; i < 8; i++) {
        float hv = h[i];
        acc += silu_f(hv) * s_bw2[i];
        float s2  = (hv + 2.2f) * 2.5f;
        float jf2 = floorf(s2);
        int j2 = (int)jf2;
        if (j2 >= 0 && j2 <= 10) {
            float b[4];
            spline_basis(s2, jf2, b);
            const float* row = s_w2[i];
            #pragma unroll
            for (int m = 0; m < 4; m++)
                acc = fmaf(b[m], row[j2 + m], acc);   // col in [0,13]
        }
    }
    return acc;
}

__global__ __launch_bounds__(TPB)
void kan_fused_kernel(const float4* __restrict__ xv, float4* __restrict__ outv,
                      const float* __restrict__ bw1, const float* __restrict__ sw1,
                      const float* __restrict__ sc1, const float* __restrict__ bw2,
                      const float* __restrict__ sw2, const float* __restrict__ sc2,
                      int n4)
{
    __shared__ __align__(16) float4 s_lut[LUT_N];
    __shared__ __align__(16) float s_w1t[14][8];
    __shared__ __align__(16) float s_w2[8][16];
    __shared__ float s_bw1[8], s_bw2[8];

    int tid  = threadIdx.x;
    int base = blockIdx.x * (TPB * F4_PER_T) + tid;

    // 1) Stage prescaled, zero-padded weight tables (heads the critical
    //    chain — these LDGs issue first).
    if (tid < 112) {                       // s_w1t: 14 rows x 8 units
        int r = tid >> 3, o = tid & 7, ri = r - 3;
        s_w1t[r][o] = (ri >= 0 && ri < 8) ? __ldg(sw1 + o * 8 + ri) * __ldg(sc1 + o)
                                          : 0.0f;
    } else if (tid < 240) {                // s_w2: 8 units x 16 cols
        int q = tid - 112, i = q >> 4, c = q & 15, ri = c - 3;
        s_w2[i][c] = (ri >= 0 && ri < 8) ? __ldg(sw2 + i * 8 + ri) * __ldg(sc2 + i)
                                         : 0.0f;
    } else if (tid < 248) {
        s_bw1[tid - 240] = __ldg(bw1 + (tid - 240));
    } else if (tid < 256) {
        s_bw2[tid - 248] = __ldg(bw2 + (tid - 248));
    }

    // 2) Issue both x loads (independent; DRAM latency hides under build).
    int idx0 = base, idx1 = base + TPB;
    bool v0 = idx0 < n4, v1 = idx1 < n4;
    float4 xin0 = v0 ? xv[idx0] : make_float4(0.f, 0.f, 0.f, 0.f);
    float4 xin1 = v1 ? xv[idx1] : make_float4(0.f, 0.f, 0.f, 0.f);

    __syncthreads();   // weights visible

    // 3) Warp-autonomous build: warp w (w<9) owns intervals 29w..29w+28.
    //    Lane l evaluates node 29w-1+l; neighbors via shfl; lanes 0..28
    //    write Lagrange cubic coefs directly. No extra barrier, no s_y.
    {
        int warp = tid >> 5, lane = tid & 31;
        if (warp < BWARPS) {
            int node = warp * 29 - 1 + lane;                  // -1 .. 259
            float xn = fmaf((float)node, LUT_H, -8.0f);       // exact grid
            float y0 = kan_eval_smem(xn, s_w1t, s_w2, s_bw1, s_bw2);
            float y1 = __shfl_down_sync(0xffffffffu, y0, 1);
            float y2 = __shfl_down_sync(0xffffffffu, y0, 2);
            float y3 = __shfl_down_sync(0xffffffffu, y0, 3);
            int k = warp * 29 + lane;
            if (lane < 29 && k < LUT_N) {
                // Lagrange cubic through (u=-1,y0),(0,y1),(1,y2),(2,y3):
                float c0 = y1;
                float c1 = -y0 * (1.0f/3.0f) - 0.5f * y1 + y2 - y3 * (1.0f/6.0f);
                float c2 =  0.5f * y0 - y1 + 0.5f * y2;
                float c3 = (y3 - y0) * (1.0f/6.0f) + 0.5f * (y1 - y2);
                s_lut[k] = make_float4(c0, c1, c2, c3);
            }
        }
    }
    __syncthreads();   // LUT visible

    // 4) Evaluate 8 elements (2 float4): one random LDS.128 + Horner each.
    float4 xs[F4_PER_T] = {xin0, xin1};
    float4 res[F4_PER_T];
    bool oor_any = false;
    unsigned oor_mask = 0;

    #pragma unroll
    for (int jb = 0; jb < F4_PER_T; jb++) {
        float xi[4] = {xs[jb].x, xs[jb].y, xs[jb].z, xs[jb].w};
        float r[4];
        #pragma unroll
        for (int e = 0; e < 4; e++) {
            float x = xi[e];
            float s = fmaf(x, LUT_INVH, LUT_OFS);
            float kf = floorf(s);
            int k = (int)kf;
            bool oo = (k < 0) | (k >= LUT_N);
            oor_any |= oo;
            if (oo) oor_mask |= 1u << (jb * 4 + e);
            k = max(0, min(LUT_N - 1, k));
            float u = fmaf(x, LUT_INVH, LUT_OFS - (float)k);
            float4 cf = s_lut[k];
            r[e] = fmaf(fmaf(fmaf(cf.w, u, cf.z), u, cf.y), u, cf.x);
        }
        res[jb] = make_float4(r[0], r[1], r[2], r[3]);
    }

    if (oor_any) {   // essentially never taken for N(0,1) inputs
        #pragma unroll
        for (int jb = 0; jb < F4_PER_T; jb++) {
            float* rp = (float*)&res[jb];
            const float* xp = (const float*)&xs[jb];
            #pragma unroll
            for (int e = 0; e < 4; e++)
                if (oor_mask & (1u << (jb * 4 + e)))
                    rp[e] = kan_eval_smem(xp[e], s_w1t, s_w2, s_bw1, s_bw2);
        }
    }

    if (v0) outv[idx0] = res[0];
    if (v1) outv[idx1] = res[1];
}

extern "C" void kernel_launch(void* const* d_in, const int* in_sizes, int n_in,
                              void* d_out, int out_size) {
    const float* x   = (const float*)d_in[0];
    const float* bw1 = (const float*)d_in[1];
    const float* sw1 = (const float*)d_in[2];
    const float* sc1 = (const float*)d_in[3];
    const float* bw2 = (const float*)d_in[4];
    const float* sw2 = (const float*)d_in[5];
    const float* sc2 = (const float*)d_in[6];

    int n  = in_sizes[0];   // 524288
    int n4 = n / 4;         // 131072

    int per_block = TPB * F4_PER_T;                  // 1024 float4
    int blocks = (n4 + per_block - 1) / per_block;   // 128
    kan_fused_kernel<<<blocks, TPB>>>((const float4*)x, (float4*)d_out,
                                      bw1, sw1, sc1, bw2, sw2, sc2, n4);
}

// round 15
// speedup vs baseline: 1.3397x; 1.2632x over previous
#include <cuda_runtime.h>

// ---------------------------------------------------------------------------
// 2-layer KAN (1 -> 8 -> 1) == scalar function out = f(x).
// SINGLE fused kernel, warp-autonomous build, full-chip coverage:
//   256 blocks x 256 threads (every SM busy, ~1.7 blocks/SM overlap).
//   Each block rebuilds a piecewise-cubic LUT of f on [-7,7), N=224
//   intervals (h=1/16 exact) in shared memory: warps 0..7 own 28 intervals
//   each; lane l evaluates ONE node (28w-1+l), neighbors via shfl_down,
//   lanes 0..27 write Lagrange coefs straight to s_lut. 2 barriers total.
//   Eval: 2 float4/thread (256*256*2*4 = 524288 = B exactly):
//   k=floor((x+7)*16), one LDS.128 + Horner per element.
//   x loads issued first so DRAM latency hides under the build phase.
// Exact fallback (same smem tables) for |x|>=7 — P ~ 2.6e-12 per sample.
// ---------------------------------------------------------------------------

#define LUT_N    224
#define LUT_INVH 16.0f          // 1/h, exact
#define LUT_H    (1.0f / 16.0f) // h,   exact
#define LUT_OFS  112.0f         // 7*16, exact
#define TPB      256            // 8 warps
#define F4_PER_T 2              // float4 per thread (eval phase)
#define IPW      28             // intervals per build warp (8*28 = 224)

__device__ __forceinline__ float silu_f(float x) {
    return x * __fdividef(1.0f, 1.0f + __expf(-x));
}

__device__ __forceinline__ void spline_basis(float s, float jf, float* b) {
    const float c6 = 1.0f / 6.0f;
    float t = s - jf;
    float u = 1.0f - t;
    float t2 = t * t, t3 = t2 * t;
    b[0] = u * u * u * c6;
    b[1] = (3.0f * t3 - 6.0f * t2 + 4.0f) * c6;
    b[2] = (-3.0f * t3 + 3.0f * t2 + 3.0f * t + 1.0f) * c6;
    b[3] = t3 * c6;
}

// Exact KAN eval from prescaled zero-padded smem tables (no inner bounds
// checks: row/col = spline index + 3, pads are zero == clipped bases).
__device__ __forceinline__ float kan_eval_smem(
    float x,
    const float (*s_w1t)[8],      // [14][8]: row r -> ri=r-3, prescaled sc1
    const float (*s_w2)[16],      // [8][16]: col c -> ri=c-3, prescaled sc2
    const float* s_bw1, const float* s_bw2)
{
    float si = silu_f(x);
    float h[8];
    #pragma unroll
    for (int o = 0; o < 8; o++) h[o] = si * s_bw1[o];

    float s  = (x + 2.2f) * 2.5f;
    float jf = floorf(s);
    int j = (int)jf;
    if (j >= 0 && j <= 10) {
        float b[4];
        spline_basis(s, jf, b);
        #pragma unroll
        for (int m = 0; m < 4; m++) {
            const float* row = s_w1t[j + m];   // (j-3+m)+3 in [0,13]
            float bm = b[m];
            #pragma unroll
            for (int o = 0; o < 8; o++) h[o] = fmaf(bm, row[o], h[o]);
        }
    }

    float acc = 0.0f;
    #pragma unroll
    for (int i = 0; i < 8; i++) {
        float hv = h[i];
        acc += silu_f(hv) * s_bw2[i];
        float s2  = (hv + 2.2f) * 2.5f;
        float jf2 = floorf(s2);
        int j2 = (int)jf2;
        if (j2 >= 0 && j2 <= 10) {
            float b[4];
            spline_basis(s2, jf2, b);
            const float* row = s_w2[i];
            #pragma unroll
            for (int m = 0; m < 4; m++)
                acc = fmaf(b[m], row[j2 + m], acc);   // col in [0,13]
        }
    }
    return acc;
}

__global__ __launch_bounds__(TPB)
void kan_fused_kernel(const float4* __restrict__ xv, float4* __restrict__ outv,
                      const float* __restrict__ bw1, const float* __restrict__ sw1,
                      const float* __restrict__ sc1, const float* __restrict__ bw2,
                      const float* __restrict__ sw2, const float* __restrict__ sc2,
                      int n4)
{
    __shared__ __align__(16) float4 s_lut[LUT_N];
    __shared__ __align__(16) float s_w1t[14][8];
    __shared__ __align__(16) float s_w2[8][16];
    __shared__ float s_bw1[8], s_bw2[8];

    int tid  = threadIdx.x;
    int base = blockIdx.x * (TPB * F4_PER_T) + tid;

    // 1) Stage prescaled, zero-padded weight tables (these LDGs issue first).
    if (tid < 112) {                       // s_w1t: 14 rows x 8 units
        int r = tid >> 3, o = tid & 7, ri = r - 3;
        s_w1t[r][o] = (ri >= 0 && ri < 8) ? __ldg(sw1 + o * 8 + ri) * __ldg(sc1 + o)
                                          : 0.0f;
    } else if (tid < 240) {                // s_w2: 8 units x 16 cols
        int q = tid - 112, i = q >> 4, c = q & 15, ri = c - 3;
        s_w2[i][c] = (ri >= 0 && ri < 8) ? __ldg(sw2 + i * 8 + ri) * __ldg(sc2 + i)
                                         : 0.0f;
    } else if (tid < 248) {
        s_bw1[tid - 240] = __ldg(bw1 + (tid - 240));
    } else {
        s_bw2[tid - 248] = __ldg(bw2 + (tid - 248));
    }

    // 2) Issue both x loads (independent; DRAM latency hides under build).
    int idx0 = base, idx1 = base + TPB;
    bool v0 = idx0 < n4, v1 = idx1 < n4;
    float4 xin0 = v0 ? xv[idx0] : make_float4(0.f, 0.f, 0.f, 0.f);
    float4 xin1 = v1 ? xv[idx1] : make_float4(0.f, 0.f, 0.f, 0.f);

    __syncthreads();   // weights visible

    // 3) Warp-autonomous build: warp w owns intervals 28w..28w+27.
    //    Lane l evaluates node 28w-1+l; neighbors via shfl; lanes 0..27
    //    write Lagrange cubic coefs directly. No extra barrier.
    {
        int warp = tid >> 5, lane = tid & 31;
        int node = warp * IPW - 1 + lane;                 // -1 .. 226
        float xn = fmaf((float)node, LUT_H, -7.0f);       // exact grid
        float y0 = kan_eval_smem(xn, s_w1t, s_w2, s_bw1, s_bw2);
        float y1 = __shfl_down_sync(0xffffffffu, y0, 1);
        float y2 = __shfl_down_sync(0xffffffffu, y0, 2);
        float y3 = __shfl_down_sync(0xffffffffu, y0, 3);
        if (lane < IPW) {
            int k = warp * IPW + lane;
            // Lagrange cubic through (u=-1,y0),(0,y1),(1,y2),(2,y3):
            float c0 = y1;
            float c1 = -y0 * (1.0f/3.0f) - 0.5f * y1 + y2 - y3 * (1.0f/6.0f);
            float c2 =  0.5f * y0 - y1 + 0.5f * y2;
            float c3 = (y3 - y0) * (1.0f/6.0f) + 0.5f * (y1 - y2);
            s_lut[k] = make_float4(c0, c1, c2, c3);
        }
    }
    __syncthreads();   // LUT visible

    // 4) Evaluate 8 elements (2 float4): one random LDS.128 + Horner each.
    float4 xs[F4_PER_T] = {xin0, xin1};
    float4 res[F4_PER_T];
    bool oor_any = false;
    unsigned oor_mask = 0;

    #pragma unroll
    for (int jb = 0; jb < F4_PER_T; jb++) {
        float xi[4] = {xs[jb].x, xs[jb].y, xs[jb].z, xs[jb].w};
        float r[4];
        #pragma unroll
        for (int e = 0; e < 4; e++) {
            float x = xi[e];
            float s = fmaf(x, LUT_INVH, LUT_OFS);
            float kf = floorf(s);
            int k = (int)kf;
            bool oo = (k < 0) | (k >= LUT_N);
            oor_any |= oo;
            if (oo) oor_mask |= 1u << (jb * 4 + e);
            k = max(0, min(LUT_N - 1, k));
            float u = fmaf(x, LUT_INVH, LUT_OFS - (float)k);
            float4 cf = s_lut[k];
            r[e] = fmaf(fmaf(fmaf(cf.w, u, cf.z), u, cf.y), u, cf.x);
        }
        res[jb] = make_float4(r[0], r[1], r[2], r[3]);
    }

    if (oor_any) {   // ~never taken: P(|x|>=7) ~ 2.6e-12 per sample
        #pragma unroll
        for (int jb = 0; jb < F4_PER_T; jb++) {
            float* rp = (float*)&res[jb];
            const float* xp = (const float*)&xs[jb];
            #pragma unroll
            for (int e = 0; e < 4; e++)
                if (oor_mask & (1u << (jb * 4 + e)))
                    rp[e] = kan_eval_smem(xp[e], s_w1t, s_w2, s_bw1, s_bw2);
        }
    }

    if (v0) outv[idx0] = res[0];
    if (v1) outv[idx1] = res[1];
}

extern "C" void kernel_launch(void* const* d_in, const int* in_sizes, int n_in,
                              void* d_out, int out_size) {
    const float* x   = (const float*)d_in[0];
    const float* bw1 = (const float*)d_in[1];
    const float* sw1 = (const float*)d_in[2];
    const float* sc1 = (const float*)d_in[3];
    const float* bw2 = (const float*)d_in[4];
    const float* sw2 = (const float*)d_in[5];
    const float* sc2 = (const float*)d_in[6];

    int n  = in_sizes[0];   // 524288
    int n4 = n / 4;         // 131072

    int per_block = TPB * F4_PER_T;                  // 512 float4
    int blocks = (n4 + per_block - 1) / per_block;   // 256
    kan_fused_kernel<<<blocks, TPB>>>((const float4*)x, (float4*)d_out,
                                      bw1, sw1, sc1, bw2, sw2, sc2, n4);
}

// round 17
// speedup vs baseline: 1.3592x; 1.0146x over previous
#include <cuda_runtime.h>

// ---------------------------------------------------------------------------
// 2-layer KAN (1 -> 8 -> 1) == scalar function out = f(x).
// SINGLE fused kernel, warp-autonomous build, full-chip coverage:
//   256 blocks x 256 threads (every SM busy, ~1.7 blocks/SM overlap).
//   Each block rebuilds a piecewise-cubic LUT of f on [-6,6), N=192
//   intervals (h=1/16, 6*16=96 exact) in shared memory: warps 0..6 own 29
//   intervals each (IPW=29 is the shfl-scheme maximum: lane 28 reads lane
//   31); lane l evaluates ONE node (29w-1+l), neighbors via shfl_down,
//   lanes 0..28 write Lagrange coefs straight to s_lut. 2 barriers total.
//   Eval: 2 float4/thread (256*256*2*4 = 524288 = B exactly):
//   k=floor((x+6)*16), one LDS.128 + Horner per element.
//   x loads issued first so their latency hides under the build phase.
// Exact fallback (same smem tables) for |x|>=6 — P ~ 2e-9 per sample.
// ---------------------------------------------------------------------------

#define LUT_N    192
#define LUT_INVH 16.0f          // 1/h, exact
#define LUT_H    (1.0f / 16.0f) // h,   exact
#define LUT_OFS  96.0f          // 6*16, exact
#define X0       (-6.0f)
#define TPB      256            // 8 warps
#define F4_PER_T 2              // float4 per thread (eval phase)
#define IPW      29             // intervals per build warp (shfl max)
#define BWARPS   7              // build warps: 7*29 = 203 >= 192

__device__ __forceinline__ float silu_f(float x) {
    return x * __fdividef(1.0f, 1.0f + __expf(-x));
}

__device__ __forceinline__ void spline_basis(float s, float jf, float* b) {
    const float c6 = 1.0f / 6.0f;
    float t = s - jf;
    float u = 1.0f - t;
    float t2 = t * t, t3 = t2 * t;
    b[0] = u * u * u * c6;
    b[1] = (3.0f * t3 - 6.0f * t2 + 4.0f) * c6;
    b[2] = (-3.0f * t3 + 3.0f * t2 + 3.0f * t + 1.0f) * c6;
    b[3] = t3 * c6;
}

// Exact KAN eval from prescaled zero-padded smem tables (no inner bounds
// checks: row/col = spline index + 3, pads are zero == clipped bases).
__device__ __forceinline__ float kan_eval_smem(
    float x,
    const float (*s_w1t)[8],      // [14][8]: row r -> ri=r-3, prescaled sc1
    const float (*s_w2)[16],      // [8][16]: col c -> ri=c-3, prescaled sc2
    const float* s_bw1, const float* s_bw2)
{
    float si = silu_f(x);
    float h[8];
    #pragma unroll
    for (int o = 0; o < 8; o++) h[o] = si * s_bw1[o];

    float s  = (x + 2.2f) * 2.5f;
    float jf = floorf(s);
    int j = (int)jf;
    if (j >= 0 && j <= 10) {
        float b[4];
        spline_basis(s, jf, b);
        #pragma unroll
        for (int m = 0; m < 4; m++) {
            const float* row = s_w1t[j + m];   // (j-3+m)+3 in [0,13]
            float bm = b[m];
            #pragma unroll
            for (int o = 0; o < 8; o++) h[o] = fmaf(bm, row[o], h[o]);
        }
    }

    float acc = 0.0f;
    #pragma unroll
    for (int i = 0; i < 8; i++) {
        float hv = h[i];
        acc += silu_f(hv) * s_bw2[i];
        float s2  = (hv + 2.2f) * 2.5f;
        float jf2 = floorf(s2);
        int j2 = (int)jf2;
        if (j2 >= 0 && j2 <= 10) {
            float b[4];
            spline_basis(s2, jf2, b);
            const float* row = s_w2[i];
            #pragma unroll
            for (int m = 0; m < 4; m++)
                acc = fmaf(b[m], row[j2 + m], acc);   // col in [0,13]
        }
    }
    return acc;
}

__global__ __launch_bounds__(TPB)
void kan_fused_kernel(const float4* __restrict__ xv, float4* __restrict__ outv,
                      const float* __restrict__ bw1, const float* __restrict__ sw1,
                      const float* __restrict__ sc1, const float* __restrict__ bw2,
                      const float* __restrict__ sw2, const float* __restrict__ sc2,
                      int n4)
{
    __shared__ __align__(16) float4 s_lut[LUT_N];
    __shared__ __align__(16) float s_w1t[14][8];
    __shared__ __align__(16) float s_w2[8][16];
    __shared__ float s_bw1[8], s_bw2[8];

    int tid  = threadIdx.x;
    int base = blockIdx.x * (TPB * F4_PER_T) + tid;

    // 1) Stage prescaled, zero-padded weight tables (these LDGs issue first).
    if (tid < 112) {                       // s_w1t: 14 rows x 8 units
        int r = tid >> 3, o = tid & 7, ri = r - 3;
        s_w1t[r][o] = (ri >= 0 && ri < 8) ? __ldg(sw1 + o * 8 + ri) * __ldg(sc1 + o)
                                          : 0.0f;
    } else if (tid < 240) {                // s_w2: 8 units x 16 cols
        int q = tid - 112, i = q >> 4, c = q & 15, ri = c - 3;
        s_w2[i][c] = (ri >= 0 && ri < 8) ? __ldg(sw2 + i * 8 + ri) * __ldg(sc2 + i)
                                         : 0.0f;
    } else if (tid < 248) {
        s_bw1[tid - 240] = __ldg(bw1 + (tid - 240));
    } else {
        s_bw2[tid - 248] = __ldg(bw2 + (tid - 248));
    }

    // 2) Issue both x loads (independent; latency hides under build).
    int idx0 = base, idx1 = base + TPB;
    bool v0 = idx0 < n4, v1 = idx1 < n4;
    float4 xin0 = v0 ? xv[idx0] : make_float4(0.f, 0.f, 0.f, 0.f);
    float4 xin1 = v1 ? xv[idx1] : make_float4(0.f, 0.f, 0.f, 0.f);

    __syncthreads();   // weights visible

    // 3) Warp-autonomous build: warps 0..6 own intervals 29w..29w+28.
    //    Lane l evaluates node 29w-1+l; neighbors via shfl (max read:
    //    lane 28 -> lane 31, in range); lanes 0..28 write Lagrange coefs.
    {
        int warp = tid >> 5, lane = tid & 31;
        if (warp < BWARPS) {
            int node = warp * IPW - 1 + lane;                 // -1 .. 204
            float xn = fmaf((float)node, LUT_H, X0);          // exact grid
            float y0 = kan_eval_smem(xn, s_w1t, s_w2, s_bw1, s_bw2);
            float y1 = __shfl_down_sync(0xffffffffu, y0, 1);
            float y2 = __shfl_down_sync(0xffffffffu, y0, 2);
            float y3 = __shfl_down_sync(0xffffffffu, y0, 3);
            int k = warp * IPW + lane;
            if (lane < IPW && k < LUT_N) {
                // Lagrange cubic through (u=-1,y0),(0,y1),(1,y2),(2,y3):
                float c0 = y1;
                float c1 = -y0 * (1.0f/3.0f) - 0.5f * y1 + y2 - y3 * (1.0f/6.0f);
                float c2 =  0.5f * y0 - y1 + 0.5f * y2;
                float c3 = (y3 - y0) * (1.0f/6.0f) + 0.5f * (y1 - y2);
                s_lut[k] = make_float4(c0, c1, c2, c3);
            }
        }
    }
    __syncthreads();   // LUT visible

    // 4) Evaluate 8 elements (2 float4): one random LDS.128 + Horner each.
    float4 xs[F4_PER_T] = {xin0, xin1};
    float4 res[F4_PER_T];
    bool oor_any = false;
    unsigned oor_mask = 0;

    #pragma unroll
    for (int jb = 0; jb < F4_PER_T; jb++) {
        float xi[4] = {xs[jb].x, xs[jb].y, xs[jb].z, xs[jb].w};
        float r[4];
        #pragma unroll
        for (int e = 0; e < 4; e++) {
            float x = xi[e];
            float s = fmaf(x, LUT_INVH, LUT_OFS);
            float kf = floorf(s);
            int k = (int)kf;
            bool oo = (k < 0) | (k >= LUT_N);
            oor_any |= oo;
            if (oo) oor_mask |= 1u << (jb * 4 + e);
            k = max(0, min(LUT_N - 1, k));
            float u = fmaf(x, LUT_INVH, LUT_OFS - (float)k);
            float4 cf = s_lut[k];
            r[e] = fmaf(fmaf(fmaf(cf.w, u, cf.z), u, cf.y), u, cf.x);
        }
        res[jb] = make_float4(r[0], r[1], r[2], r[3]);
    }

    if (oor_any) {   // ~never taken: P(|x|>=6) ~ 2e-9 per sample
        #pragma unroll
        for (int jb = 0; jb < F4_PER_T; jb++) {
            float* rp = (float*)&res[jb];
            const float* xp = (const float*)&xs[jb];
            #pragma unroll
            for (int e = 0; e < 4; e++)
                if (oor_mask & (1u << (jb * 4 + e)))
                    rp[e] = kan_eval_smem(xp[e], s_w1t, s_w2, s_bw1, s_bw2);
        }
    }

    if (v0) outv[idx0] = res[0];
    if (v1) outv[idx1] = res[1];
}

extern "C" void kernel_launch(void* const* d_in, const int* in_sizes, int n_in,
                              void* d_out, int out_size) {
    const float* x   = (const float*)d_in[0];
    const float* bw1 = (const float*)d_in[1];
    const float* sw1 = (const float*)d_in[2];
    const float* sc1 = (const float*)d_in[3];
    const float* bw2 = (const float*)d_in[4];
    const float* sw2 = (const float*)d_in[5];
    const float* sc2 = (const float*)d_in[6];

    int n  = in_sizes[0];   // 524288
    int n4 = n / 4;         // 131072

    int per_block = TPB * F4_PER_T;                  // 512 float4
    int blocks = (n4 + per_block - 1) / per_block;   // 256
    kan_fused_kernel<<<blocks, TPB>>>((const float4*)x, (float4*)d_out,
                                      bw1, sw1, sc1, bw2, sw2, sc2, n4);
}